// round 5
// baseline (speedup 1.0000x reference)
#include <cuda_runtime.h>

// CfC / liquid-net recurrent cell, one thread per pixel.
// Shapes (fixed by setup_inputs): B=4, C=16, T=32, H=64, W=64 -> HW=4096,
// UNITS=32, BACKBONE=64.  ts == 1.0 so Wt = Wta + Wtb, bt = bta + btb.

#define CC   16
#define TT   32
#define UU   32
#define BKB  64
#define HWSZ 4096
#define NTHREADS 128
#define NPIX (4 * HWSZ)          // 16384 pixels
#define NBLOCKS (NPIX / NTHREADS) // 128

// Dynamic shared memory layout (in floats):
//  [0,     8192)  zk   [64][128]   per-thread column, conflict-free
//  [8192,  9216)  Wbx  [64][16]    backbone rows, x part (row-major)
//  [9216, 11264)  Wbh  [64][32]    backbone rows, h part
//  [11264,13312)  W1t  [64][32]    head ff1, c-major ([c][u]) for float4 u-loads
//  [13312,15360)  W2t  [64][32]    head ff2
//  [15360,17408)  Wtt  [64][32]    folded time head (Wta+Wtb)
//  [17408,17472)  bb[64]
//  [17472,17504)  b1[32]
//  [17504,17536)  b2[32]
//  [17536,17568)  bt[32]  (bta+btb)
#define SMEM_FLOATS 17568

__device__ __forceinline__ float fast_tanh(float x) {
    // tanh(x) = 2/(1+e^{-2x}) - 1 ; stable at both extremes with __expf/__fdividef
    float e = __expf(-2.0f * x);
    return __fdividef(2.0f, e + 1.0f) - 1.0f;
}
__device__ __forceinline__ float fast_sig(float x) {
    return __fdividef(1.0f, 1.0f + __expf(-x));
}

__global__ void __launch_bounds__(NTHREADS, 1)
cfc_scan_kernel(const float* __restrict__ x,
                const float* __restrict__ Wb,  const float* __restrict__ bb,
                const float* __restrict__ W1,  const float* __restrict__ b1,
                const float* __restrict__ W2,  const float* __restrict__ b2,
                const float* __restrict__ Wta, const float* __restrict__ bta,
                const float* __restrict__ Wtb, const float* __restrict__ btb,
                float* __restrict__ out)
{
    extern __shared__ float sm[];
    float* s_zk  = sm;
    float* s_Wbx = sm + 8192;
    float* s_Wbh = sm + 9216;
    float* s_W1t = sm + 11264;
    float* s_W2t = sm + 13312;
    float* s_Wtt = sm + 15360;
    float* s_bb  = sm + 17408;
    float* s_b1  = sm + 17472;
    float* s_b2  = sm + 17504;
    float* s_bt  = sm + 17536;

    const int tid = threadIdx.x;

    // ---- stage weights into shared memory ----
    for (int i = tid; i < BKB * 48; i += NTHREADS) {
        int k = i / 48, c = i % 48;
        float v = Wb[i];
        if (c < 16) s_Wbx[k * 16 + c] = v;
        else        s_Wbh[k * 32 + (c - 16)] = v;
    }
    for (int i = tid; i < UU * BKB; i += NTHREADS) {
        int u = i / BKB, c = i % BKB;       // W row-major: [u][c]
        s_W1t[c * UU + u] = W1[i];
        s_W2t[c * UU + u] = W2[i];
        s_Wtt[c * UU + u] = Wta[i] + Wtb[i];
    }
    if (tid < BKB) s_bb[tid] = bb[tid];
    if (tid < UU) { s_b1[tid] = b1[tid]; s_b2[tid] = b2[tid]; s_bt[tid] = bta[tid] + btb[tid]; }
    __syncthreads();

    // ---- per-thread pixel ----
    const int p  = blockIdx.x * NTHREADS + tid;   // 0..16383 exactly
    const int b  = p >> 12;                       // / 4096
    const int hw = p & 4095;
    const float* xb = x   + ((size_t)b * CC) * (TT * HWSZ) + hw;  // x[b,c,t,hw]
    float*       ob = out + ((size_t)b * UU) * (TT * HWSZ) + hw;  // out[b,u,t,hw]

    float h[UU];
#pragma unroll
    for (int u = 0; u < UU; u++) h[u] = 0.0f;

    for (int t = 0; t < TT; t++) {
        // load this step's x channels (coalesced across lanes, 16 independent LDGs)
        float xv[CC];
#pragma unroll
        for (int c = 0; c < CC; c++) xv[c] = xb[(c * TT + t) * HWSZ];

        // ---- backbone: zk[k] = lecun_tanh(Wbx@x + Wbh@h + bb) ----
#pragma unroll 2
        for (int k = 0; k < BKB; k++) {
            const float4* wx = (const float4*)(s_Wbx + k * 16);
            const float4* wh = (const float4*)(s_Wbh + k * 32);
            float a0 = s_bb[k], a1s = 0.0f, a2s = 0.0f, a3s = 0.0f;  // 4 chains
#pragma unroll
            for (int c4 = 0; c4 < 4; c4++) {
                float4 w = wx[c4];
                a0  += w.x * xv[c4 * 4 + 0];
                a1s += w.y * xv[c4 * 4 + 1];
                a2s += w.z * xv[c4 * 4 + 2];
                a3s += w.w * xv[c4 * 4 + 3];
            }
#pragma unroll
            for (int c4 = 0; c4 < 8; c4++) {
                float4 w = wh[c4];
                a0  += w.x * h[c4 * 4 + 0];
                a1s += w.y * h[c4 * 4 + 1];
                a2s += w.z * h[c4 * 4 + 2];
                a3s += w.w * h[c4 * 4 + 3];
            }
            float acc = (a0 + a1s) + (a2s + a3s);
            s_zk[k * NTHREADS + tid] = 1.7159f * fast_tanh(0.666f * acc);
        }
        // zk column is thread-private: no sync needed.

        // ---- heads: ff1/ff2/t in groups of 8 output units ----
#pragma unroll
        for (int g = 0; g < 4; g++) {
            const int u0 = g * 8;
            float a1[8], a2[8], at[8];
#pragma unroll
            for (int j = 0; j < 8; j++) {
                a1[j] = s_b1[u0 + j];
                a2[j] = s_b2[u0 + j];
                at[j] = s_bt[u0 + j];
            }
#pragma unroll 4
            for (int c = 0; c < BKB; c++) {
                float q = s_zk[c * NTHREADS + tid];
                float4 w1a = *(const float4*)(s_W1t + c * UU + u0);
                float4 w1b = *(const float4*)(s_W1t + c * UU + u0 + 4);
                float4 w2a = *(const float4*)(s_W2t + c * UU + u0);
                float4 w2b = *(const float4*)(s_W2t + c * UU + u0 + 4);
                float4 wta = *(const float4*)(s_Wtt + c * UU + u0);
                float4 wtb = *(const float4*)(s_Wtt + c * UU + u0 + 4);
                a1[0] += w1a.x * q; a1[1] += w1a.y * q; a1[2] += w1a.z * q; a1[3] += w1a.w * q;
                a1[4] += w1b.x * q; a1[5] += w1b.y * q; a1[6] += w1b.z * q; a1[7] += w1b.w * q;
                a2[0] += w2a.x * q; a2[1] += w2a.y * q; a2[2] += w2a.z * q; a2[3] += w2a.w * q;
                a2[4] += w2b.x * q; a2[5] += w2b.y * q; a2[6] += w2b.z * q; a2[7] += w2b.w * q;
                at[0] += wta.x * q; at[1] += wta.y * q; at[2] += wta.z * q; at[3] += wta.w * q;
                at[4] += wtb.x * q; at[5] += wtb.y * q; at[6] += wtb.z * q; at[7] += wtb.w * q;
            }
#pragma unroll
            for (int j = 0; j < 8; j++) {
                float f1 = fast_tanh(a1[j]);
                float f2 = fast_tanh(a2[j]);
                float ti = fast_sig(at[j]);         // sigmoid(t_a*1 + t_b)
                float hn = f1 + ti * (f2 - f1);      // ff1*(1-ti) + ti*ff2
                h[u0 + j] = hn;
                ob[((u0 + j) * TT + t) * HWSZ] = hn; // out[b,u,t,hw]
            }
        }
    }
}

extern "C" void kernel_launch(void* const* d_in, const int* in_sizes, int n_in,
                              void* d_out, int out_size)
{
    const float* x   = (const float*)d_in[0];
    const float* Wb  = (const float*)d_in[1];
    const float* bb  = (const float*)d_in[2];
    const float* W1  = (const float*)d_in[3];
    const float* b1  = (const float*)d_in[4];
    const float* W2  = (const float*)d_in[5];
    const float* b2  = (const float*)d_in[6];
    const float* Wta = (const float*)d_in[7];
    const float* bta = (const float*)d_in[8];
    const float* Wtb = (const float*)d_in[9];
    const float* btb = (const float*)d_in[10];
    float* out = (float*)d_out;

    size_t smem = SMEM_FLOATS * sizeof(float);   // ~68.6 KB -> needs opt-in
    cudaFuncSetAttribute(cfc_scan_kernel,
                         cudaFuncAttributeMaxDynamicSharedMemorySize, (int)smem);

    cfc_scan_kernel<<<NBLOCKS, NTHREADS, smem>>>(
        x, Wb, bb, W1, b1, W2, b2, Wta, bta, Wtb, btb, out);
}

// round 7
// speedup vs baseline: 1.0410x; 1.0410x over previous
#include <cuda_runtime.h>

// CfC / liquid-net recurrent cell, one thread per pixel, packed f32x2 math.
// Shapes: B=4, C=16, T=32, H=64, W=64 -> HW=4096; UNITS=32, BACKBONE=64.
// ts == 1.0 so Wt = Wta + Wtb, bt = bta + btb.

#define CC   16
#define TT   32
#define UU   32
#define BKB  64
#define HWSZ 4096
#define NTHREADS 128
#define NBLOCKS  128            // 128*128 = 16384 pixels exactly

typedef unsigned long long u64;

// ---- packed fp32x2 primitives (SASS FFMA2 path, ptxas won't emit it itself) ----
__device__ __forceinline__ void ffma2(u64& d, u64 a, u64 b) {
    asm("fma.rn.f32x2 %0, %1, %2, %0;" : "+l"(d) : "l"(a), "l"(b));
}
__device__ __forceinline__ u64 fadd2(u64 a, u64 b) {
    u64 d; asm("add.rn.f32x2 %0, %1, %2;" : "=l"(d) : "l"(a), "l"(b)); return d;
}
__device__ __forceinline__ u64 pack2(float lo, float hi) {
    u64 d; asm("mov.b64 %0, {%1, %2};" : "=l"(d) : "f"(lo), "f"(hi)); return d;
}
__device__ __forceinline__ void unpack2(u64 v, float& lo, float& hi) {
    asm("mov.b64 {%0, %1}, %2;" : "=f"(lo), "=f"(hi) : "l"(v));
}

__device__ __forceinline__ float fast_tanh(float x) {
    float e = __expf(-2.0f * x);
    return __fdividef(2.0f, e + 1.0f) - 1.0f;
}
__device__ __forceinline__ float fast_sig(float x) {
    return __fdividef(1.0f, 1.0f + __expf(-x));
}

// Dynamic shared memory layout:
//   u64   s_zkq [64][128]   duplicated-packed zk (z,z), per-thread column   64 KB
//   float region (after the u64 region), offsets in floats:
//     Wbx  [0,1024)      backbone rows, x part   [k][16]
//     Wbh  [1024,3072)   backbone rows, h part   [k][32]
//     W1t  [3072,5120)   head ff1, c-major [c][32]
//     W2t  [5120,7168)   head ff2
//     Wtt  [7168,9216)   folded time head (Wta+Wtb)
//     bb   [9216,9280)
//     b1   [9280,9312)  b2 [9312,9344)  bt [9344,9376)
#define ZKQ_U64   (BKB * NTHREADS)            // 8192 u64 = 64 KB
#define FREG_FLOATS 9376
#define SMEM_BYTES (ZKQ_U64 * 8 + FREG_FLOATS * 4)   // 103040

__global__ void __launch_bounds__(NTHREADS, 1)
cfc_scan_kernel(const float* __restrict__ x,
                const float* __restrict__ Wb,  const float* __restrict__ bb,
                const float* __restrict__ W1,  const float* __restrict__ b1,
                const float* __restrict__ W2,  const float* __restrict__ b2,
                const float* __restrict__ Wta, const float* __restrict__ bta,
                const float* __restrict__ Wtb, const float* __restrict__ btb,
                float* __restrict__ out)
{
    extern __shared__ u64 smq[];
    u64*   s_zkq = smq;
    float* sm_f  = (float*)(smq + ZKQ_U64);
    float* s_Wbx = sm_f;
    float* s_Wbh = sm_f + 1024;
    float* s_W1t = sm_f + 3072;
    float* s_W2t = sm_f + 5120;
    float* s_Wtt = sm_f + 7168;
    float* s_bb  = sm_f + 9216;
    float* s_b1  = sm_f + 9280;
    float* s_b2  = sm_f + 9312;
    float* s_bt  = sm_f + 9344;

    const int tid = threadIdx.x;

    // ---- stage weights into shared memory ----
    for (int i = tid; i < BKB * 48; i += NTHREADS) {
        int k = i / 48, c = i % 48;
        float v = Wb[i];
        if (c < 16) s_Wbx[k * 16 + c] = v;
        else        s_Wbh[k * 32 + (c - 16)] = v;
    }
    for (int i = tid; i < UU * BKB; i += NTHREADS) {
        int u = i / BKB, c = i % BKB;          // W row-major [u][c] -> c-major [c][u]
        s_W1t[c * UU + u] = W1[i];
        s_W2t[c * UU + u] = W2[i];
        s_Wtt[c * UU + u] = Wta[i] + Wtb[i];
    }
    if (tid < BKB) s_bb[tid] = bb[tid];
    if (tid < UU) { s_b1[tid] = b1[tid]; s_b2[tid] = b2[tid]; s_bt[tid] = bta[tid] + btb[tid]; }
    __syncthreads();

    // ---- per-thread pixel ----
    const int p  = blockIdx.x * NTHREADS + tid;   // 0..16383
    const int b  = p >> 12;
    const int hw = p & 4095;
    const float* xb = x   + ((size_t)b * CC) * (TT * HWSZ) + hw;   // x[b,c,t,hw]
    float*       ob = out + ((size_t)b * UU) * (TT * HWSZ) + hw;   // out[b,u,t,hw]
    u64* zcol = s_zkq + tid;

    u64 hp[UU / 2];                     // h packed pairs: hp[j] = (h[2j], h[2j+1])
#pragma unroll
    for (int j = 0; j < UU / 2; j++) hp[j] = 0ull;

    for (int t = 0; t < TT; t++) {
        // load + pack this step's x channels (coalesced across lanes)
        float xv[CC];
#pragma unroll
        for (int c = 0; c < CC; c++) xv[c] = xb[(c * TT + t) * HWSZ];
        u64 xp[CC / 2];
#pragma unroll
        for (int j = 0; j < CC / 2; j++) xp[j] = pack2(xv[2 * j], xv[2 * j + 1]);

        // ---- backbone: zk[k] = lecun_tanh(Wbx@x + Wbh@h + bb) ----
#pragma unroll 4
        for (int k = 0; k < BKB; k++) {
            const ulonglong2* wx = (const ulonglong2*)(s_Wbx + k * 16);
            const ulonglong2* wh = (const ulonglong2*)(s_Wbh + k * 32);
            u64 a0 = 0ull, a1 = 0ull, a2 = 0ull, a3 = 0ull;
#pragma unroll
            for (int j = 0; j < 4; j++) {
                ulonglong2 w = wx[j];                 // floats 4j..4j+3
                ffma2(a0, w.x, xp[2 * j]);
                ffma2(a1, w.y, xp[2 * j + 1]);
            }
#pragma unroll
            for (int j = 0; j < 4; j++) {
                ulonglong2 w0 = wh[2 * j];
                ulonglong2 w1 = wh[2 * j + 1];
                ffma2(a2, w0.x, hp[4 * j]);
                ffma2(a3, w0.y, hp[4 * j + 1]);
                ffma2(a0, w1.x, hp[4 * j + 2]);
                ffma2(a1, w1.y, hp[4 * j + 3]);
            }
            u64 s = fadd2(fadd2(a0, a1), fadd2(a2, a3));
            float lo, hi; unpack2(s, lo, hi);
            float acc = lo + hi + s_bb[k];
            float z = 1.7159f * fast_tanh(0.666f * acc);
            zcol[k * NTHREADS] = pack2(z, z);        // duplicated-packed, no sync needed
        }

        // ---- heads: two groups of 16 units, all three heads fused ----
        for (int g = 0; g < 2; g++) {
            const int u0 = g * 16;
            u64 A1[8], A2[8], AT[8];
#pragma unroll
            for (int j = 0; j < 8; j++) { A1[j] = 0ull; A2[j] = 0ull; AT[j] = 0ull; }
#pragma unroll 4
            for (int c = 0; c < BKB; c++) {
                u64 qq = zcol[c * NTHREADS];          // (z, z)
                const ulonglong2* w1p = (const ulonglong2*)(s_W1t + c * UU + u0);
                const ulonglong2* w2p = (const ulonglong2*)(s_W2t + c * UU + u0);
                const ulonglong2* wtp = (const ulonglong2*)(s_Wtt + c * UU + u0);
#pragma unroll
                for (int m = 0; m < 4; m++) {
                    ulonglong2 w1 = w1p[m];
                    ffma2(A1[2 * m], w1.x, qq); ffma2(A1[2 * m + 1], w1.y, qq);
                    ulonglong2 w2 = w2p[m];
                    ffma2(A2[2 * m], w2.x, qq); ffma2(A2[2 * m + 1], w2.y, qq);
                    ulonglong2 wt = wtp[m];
                    ffma2(AT[2 * m], wt.x, qq); ffma2(AT[2 * m + 1], wt.y, qq);
                }
            }
#pragma unroll
            for (int j = 0; j < 8; j++) {
                const int u = u0 + 2 * j;
                float p0, p1, q0, q1, r0, r1;
                unpack2(A1[j], p0, p1);
                unpack2(A2[j], q0, q1);
                unpack2(AT[j], r0, r1);
                float f10 = fast_tanh(p0 + s_b1[u]);
                float f11 = fast_tanh(p1 + s_b1[u + 1]);
                float f20 = fast_tanh(q0 + s_b2[u]);
                float f21 = fast_tanh(q1 + s_b2[u + 1]);
                float ti0 = fast_sig(r0 + s_bt[u]);
                float ti1 = fast_sig(r1 + s_bt[u + 1]);
                float h0 = f10 + ti0 * (f20 - f10);   // ff1*(1-ti) + ti*ff2
                float h1 = f11 + ti1 * (f21 - f11);
                hp[g * 8 + j] = pack2(h0, h1);
                ob[((u) * TT + t) * HWSZ]     = h0;
                ob[((u + 1) * TT + t) * HWSZ] = h1;
            }
        }
    }
}

extern "C" void kernel_launch(void* const* d_in, const int* in_sizes, int n_in,
                              void* d_out, int out_size)
{
    const float* x   = (const float*)d_in[0];
    const float* Wb  = (const float*)d_in[1];
    const float* bb  = (const float*)d_in[2];
    const float* W1  = (const float*)d_in[3];
    const float* b1  = (const float*)d_in[4];
    const float* W2  = (const float*)d_in[5];
    const float* b2  = (const float*)d_in[6];
    const float* Wta = (const float*)d_in[7];
    const float* bta = (const float*)d_in[8];
    const float* Wtb = (const float*)d_in[9];
    const float* btb = (const float*)d_in[10];
    float* out = (float*)d_out;

    cudaFuncSetAttribute(cfc_scan_kernel,
                         cudaFuncAttributeMaxDynamicSharedMemorySize, SMEM_BYTES);

    cfc_scan_kernel<<<NBLOCKS, NTHREADS, SMEM_BYTES>>>(
        x, Wb, bb, W1, b1, W2, b2, Wta, bta, Wtb, btb, out);
}